// round 1
// baseline (speedup 1.0000x reference)
#include <cuda_runtime.h>
#include <cstdint>

#define F 128
#define NMAX 100000

// Scratch (device globals — no allocation allowed in kernel_launch)
__device__ float g_T1[(size_t)NMAX * F];
__device__ float g_T2[(size_t)NMAX * F];
__device__ float g_T3[(size_t)NMAX * F];
__device__ float g_Wt[4 * F * F];   // Wt[k][f][o] = W[o][f*4+k]

// ---------------------------------------------------------------------------
// W permutation: W is [F_OUT=128, F_IN*K=512] with inner index f*4+k.
// Produce Wt[k*128*128 + f*128 + o] so GEMM B-tiles load coalesced in o.
// ---------------------------------------------------------------------------
__global__ void prep_w_kernel(const float* __restrict__ W) {
    int idx = blockIdx.x * blockDim.x + threadIdx.x;
    if (idx >= 4 * F * F) return;
    int o = idx & 127;
    int f = (idx >> 7) & 127;
    int k = idx >> 14;
    g_Wt[k * F * F + f * F + o] = W[o * 512 + f * 4 + k];
}

// T1 = 0 ; T2 = -x   (folds the "- T0" of the K=2 recurrence into init)
__global__ void init_t1_t2_kernel(const float4* __restrict__ x4, int n4) {
    int i = blockIdx.x * blockDim.x + threadIdx.x;
    if (i >= n4) return;
    ((float4*)g_T1)[i] = make_float4(0.f, 0.f, 0.f, 0.f);
    float4 v = x4[i];
    ((float4*)g_T2)[i] = make_float4(-v.x, -v.y, -v.z, -v.w);
}

// T3 = -T1  (folds the "- T1" of the K=3 recurrence; runs after spmm1)
__global__ void init_t3_kernel(int n4) {
    int i = blockIdx.x * blockDim.x + threadIdx.x;
    if (i >= n4) return;
    float4 v = ((const float4*)g_T1)[i];
    ((float4*)g_T3)[i] = make_float4(-v.x, -v.y, -v.z, -v.w);
}

// ---------------------------------------------------------------------------
// COO SpMM with vectorized global reductions.
// One warp handles 4 edges; each lane covers 4 of the 128 features (float4).
// dst[row] += scale * val * src[col]   via red.global.add.v4.f32
// ---------------------------------------------------------------------------
__global__ void __launch_bounds__(256) spmm_atomic_kernel(
    const int*   __restrict__ rows,
    const int*   __restrict__ cols,
    const float* __restrict__ vals,
    const float* __restrict__ src,
    float*       __restrict__ dst,
    int nE, float scale)
{
    int gw   = (blockIdx.x * blockDim.x + threadIdx.x) >> 5;
    int lane = threadIdx.x & 31;
    int base = gw * 4;
    if (base >= nE) return;

    int   r[4], c[4];
    float v[4];
#pragma unroll
    for (int j = 0; j < 4; j++) {
        int e = base + j;
        bool ok = e < nE;
        r[j] = ok ? __ldg(rows + e) : 0;
        c[j] = ok ? __ldg(cols + e) : 0;
        v[j] = ok ? __ldg(vals + e) * scale : 0.0f;
    }

    float4 xv[4];
#pragma unroll
    for (int j = 0; j < 4; j++)
        xv[j] = __ldg((const float4*)(src + (size_t)c[j] * F) + lane);

#pragma unroll
    for (int j = 0; j < 4; j++) {
        float* p = dst + (size_t)r[j] * F + lane * 4;
        float a = v[j] * xv[j].x;
        float b = v[j] * xv[j].y;
        float cc = v[j] * xv[j].z;
        float d = v[j] * xv[j].w;
        asm volatile("red.global.add.v4.f32 [%0], {%1, %2, %3, %4};"
                     :: "l"(p), "f"(a), "f"(b), "f"(cc), "f"(d)
                     : "memory");
    }
}

// ---------------------------------------------------------------------------
// Dense GEMM: out[n,o] = b[o] + sum_{t=0..3} sum_f Tt[n,f] * Wt[t][f][o]
// BM=128, BN=128, BK=16, 256 threads, 8x8 microtiles.
// ---------------------------------------------------------------------------
__global__ void __launch_bounds__(256) gemm_kernel(
    const float* __restrict__ x,
    const float* __restrict__ T1,
    const float* __restrict__ T2,
    const float* __restrict__ T3,
    const float* __restrict__ Wt,
    const float* __restrict__ bias,
    float*       __restrict__ out,
    int nRows)
{
    __shared__ float As[16][132];   // A tile stored transposed [k][m], pad 4
    __shared__ float Ws[16][128];

    const int tid = threadIdx.x;
    const int m0  = blockIdx.x * 128;
    const int rm  = (tid >> 4) << 3;   // 0..120
    const int rn  = (tid & 15) << 3;   // 0..120

    float acc[8][8];
#pragma unroll
    for (int i = 0; i < 8; i++)
#pragma unroll
        for (int j = 0; j < 8; j++) acc[i][j] = 0.f;

    const float* srcs[4] = { x, T1, T2, T3 };

    for (int t = 0; t < 4; t++) {
        const float* A   = srcs[t];
        const float* Wtt = Wt + t * (F * F);
#pragma unroll 1
        for (int kc = 0; kc < 8; kc++) {
            __syncthreads();
            // load A tile: 128 rows x 16 cols -> As[f_local][m_local]
#pragma unroll
            for (int rr = 0; rr < 2; rr++) {
                int mloc = (tid >> 2) + rr * 64;
                int m    = m0 + mloc;
                int f    = (kc << 4) + ((tid & 3) << 2);
                float4 va = make_float4(0.f, 0.f, 0.f, 0.f);
                if (m < nRows)
                    va = __ldg((const float4*)(A + (size_t)m * F + f));
                int fl = (tid & 3) << 2;
                As[fl + 0][mloc] = va.x;
                As[fl + 1][mloc] = va.y;
                As[fl + 2][mloc] = va.z;
                As[fl + 3][mloc] = va.w;
            }
            // load W tile: 16 x 128, fully coalesced
#pragma unroll
            for (int rr = 0; rr < 2; rr++) {
                int idx = tid + rr * 256;      // 0..511 float4 slots
                int f   = idx >> 5;            // 128 floats / 4 = 32 vec per row
                int o   = (idx & 31) << 2;
                *(float4*)&Ws[f][o] =
                    __ldg((const float4*)(Wtt + ((kc << 4) + f) * F + o));
            }
            __syncthreads();

#pragma unroll
            for (int kk = 0; kk < 16; kk++) {
                float4 a0 = *(const float4*)&As[kk][rm];
                float4 a1 = *(const float4*)&As[kk][rm + 4];
                float4 w0 = *(const float4*)&Ws[kk][rn];
                float4 w1 = *(const float4*)&Ws[kk][rn + 4];
                float a[8] = { a0.x, a0.y, a0.z, a0.w, a1.x, a1.y, a1.z, a1.w };
                float w[8] = { w0.x, w0.y, w0.z, w0.w, w1.x, w1.y, w1.z, w1.w };
#pragma unroll
                for (int i = 0; i < 8; i++)
#pragma unroll
                    for (int j = 0; j < 8; j++)
                        acc[i][j] += a[i] * w[j];
            }
        }
    }

    float4 b0 = __ldg((const float4*)(bias + rn));
    float4 b1 = __ldg((const float4*)(bias + rn + 4));
    float bb[8] = { b0.x, b0.y, b0.z, b0.w, b1.x, b1.y, b1.z, b1.w };

#pragma unroll
    for (int i = 0; i < 8; i++) {
        int m = m0 + rm + i;
        if (m < nRows) {
            float4 o0 = make_float4(acc[i][0] + bb[0], acc[i][1] + bb[1],
                                    acc[i][2] + bb[2], acc[i][3] + bb[3]);
            float4 o1 = make_float4(acc[i][4] + bb[4], acc[i][5] + bb[5],
                                    acc[i][6] + bb[6], acc[i][7] + bb[7]);
            *(float4*)(out + (size_t)m * F + rn)     = o0;
            *(float4*)(out + (size_t)m * F + rn + 4) = o1;
        }
    }
}

// ---------------------------------------------------------------------------
extern "C" void kernel_launch(void* const* d_in, const int* in_sizes, int n_in,
                              void* d_out, int out_size)
{
    const float* x    = (const float*)d_in[0];
    const int*   rows = (const int*)  d_in[1];
    const int*   cols = (const int*)  d_in[2];
    const float* vals = (const float*)d_in[3];
    const float* W    = (const float*)d_in[4];
    const float* b    = (const float*)d_in[5];
    float* out = (float*)d_out;

    int N = in_sizes[0] / F;
    int E = in_sizes[1];

    void *pT1, *pT2, *pT3, *pWt;
    cudaGetSymbolAddress(&pT1, g_T1);
    cudaGetSymbolAddress(&pT2, g_T2);
    cudaGetSymbolAddress(&pT3, g_T3);
    cudaGetSymbolAddress(&pWt, g_Wt);
    float* T1 = (float*)pT1;
    float* T2 = (float*)pT2;
    float* T3 = (float*)pT3;
    float* Wt = (float*)pWt;

    // W permute
    prep_w_kernel<<<(4 * F * F + 255) / 256, 256>>>(W);

    // T1 = 0, T2 = -x
    int n4 = (N * F) / 4;
    init_t1_t2_kernel<<<(n4 + 255) / 256, 256>>>((const float4*)x, n4);

    int warps   = (E + 3) / 4;
    int sblocks = (warps + 7) / 8;   // 8 warps / block of 256 threads

    // T1 += L x
    spmm_atomic_kernel<<<sblocks, 256>>>(rows, cols, vals, x, T1, E, 1.0f);
    // T3 = -T1
    init_t3_kernel<<<(n4 + 255) / 256, 256>>>(n4);
    // T2 += 2 L T1   (T2 was init'd to -x)
    spmm_atomic_kernel<<<sblocks, 256>>>(rows, cols, vals, T1, T2, E, 2.0f);
    // T3 += 2 L T2   (T3 was init'd to -T1)
    spmm_atomic_kernel<<<sblocks, 256>>>(rows, cols, vals, T2, T3, E, 2.0f);

    // out = [x|T1|T2|T3] @ W^T + b
    int gblocks = (N + 127) / 128;
    gemm_kernel<<<gblocks, 256>>>(x, T1, T2, T3, Wt, b, out, N);
}

// round 2
// speedup vs baseline: 1.7093x; 1.7093x over previous
#include <cuda_runtime.h>
#include <cstdint>

#define F 128
#define NMAX 100000
#define EMAX 3200000

// ---------------------------------------------------------------------------
// Device scratch (no allocation allowed in kernel_launch)
// ---------------------------------------------------------------------------
__device__ float g_T1[(size_t)NMAX * F];
__device__ float g_T2[(size_t)NMAX * F];
__device__ float g_T3[(size_t)NMAX * F];
__device__ float g_Wt[4 * F * F];          // Wt[k][f][o] = W[o][f*4+k]
__device__ int   g_hist[NMAX];             // per-row edge counts
__device__ int   g_rowptr[NMAX + 1];       // CSR row pointers
__device__ int   g_cursor[NMAX];           // scatter cursors
__device__ int2  g_edges[EMAX];            // row-sorted {col, val-as-int}
__device__ int   g_bsum[128];              // block sums for scan

// ---------------------------------------------------------------------------
// CSR build
// ---------------------------------------------------------------------------
__global__ void zero_hist_kernel(int n) {
    int i = blockIdx.x * blockDim.x + threadIdx.x;
    if (i < n) g_hist[i] = 0;
}

__global__ void hist_kernel(const int* __restrict__ rows, int nE) {
    int e = blockIdx.x * blockDim.x + threadIdx.x;
    if (e < nE) atomicAdd(&g_hist[rows[e]], 1);
}

// per-block exclusive scan of 1024 counts -> g_rowptr (local), block total -> g_bsum
__global__ void scan1_kernel(int n) {
    __shared__ int s[1024];
    int t = threadIdx.x;
    int i = blockIdx.x * 1024 + t;
    int cnt = (i < n) ? g_hist[i] : 0;
    s[t] = cnt;
    __syncthreads();
#pragma unroll
    for (int off = 1; off < 1024; off <<= 1) {
        int v = (t >= off) ? s[t - off] : 0;
        __syncthreads();
        s[t] += v;
        __syncthreads();
    }
    if (i < n) g_rowptr[i] = s[t] - cnt;   // exclusive
    if (t == 1023) g_bsum[blockIdx.x] = s[1023];
}

__global__ void scan2_kernel(int nBlocks, int nE, int n) {
    if (threadIdx.x == 0) {
        int run = 0;
        for (int i = 0; i < nBlocks; i++) {
            int v = g_bsum[i];
            g_bsum[i] = run;
            run += v;
        }
        g_rowptr[n] = nE;
    }
}

__global__ void scan3_kernel(int n) {
    int i = blockIdx.x * 1024 + threadIdx.x;
    if (i < n) {
        int v = g_rowptr[i] + g_bsum[i >> 10];
        g_rowptr[i] = v;
        g_cursor[i] = v;
    }
}

__global__ void scatter_kernel(const int* __restrict__ rows,
                               const int* __restrict__ cols,
                               const float* __restrict__ vals, int nE) {
    int e = blockIdx.x * blockDim.x + threadIdx.x;
    if (e >= nE) return;
    int r = rows[e];
    int pos = atomicAdd(&g_cursor[r], 1);
    g_edges[pos] = make_int2(cols[e], __float_as_int(vals[e]));
}

// ---------------------------------------------------------------------------
// W permutation: W is [128, 512] with inner index f*4+k -> Wt[k][f][o]
// ---------------------------------------------------------------------------
__global__ void prep_w_kernel(const float* __restrict__ W) {
    int idx = blockIdx.x * blockDim.x + threadIdx.x;
    if (idx >= 4 * F * F) return;
    int o = idx & 127;
    int f = (idx >> 7) & 127;
    int k = idx >> 14;
    g_Wt[k * F * F + f * F + o] = W[o * 512 + f * 4 + k];
}

// ---------------------------------------------------------------------------
// CSR SpMM, warp-per-row, register accumulation.
// dst[r] = alpha * sum_e val[e]*src[col[e]]  +  beta * prev[r]
// ---------------------------------------------------------------------------
__global__ void __launch_bounds__(256) spmm_csr_kernel(
    const float* __restrict__ src,
    const float* __restrict__ prev,
    float*       __restrict__ dst,
    int N, float alpha, float beta)
{
    int row  = (blockIdx.x * blockDim.x + threadIdx.x) >> 5;
    int lane = threadIdx.x & 31;
    if (row >= N) return;

    int start = __ldg(&g_rowptr[row]);
    int end   = __ldg(&g_rowptr[row + 1]);

    const float4* src4 = (const float4*)src;
    float4 acc = make_float4(0.f, 0.f, 0.f, 0.f);

    int b = start;
    // full 32-edge batches: coalesced index load + 32 independent gathers
    for (; b + 32 <= end; b += 32) {
        int2 ev = __ldg(&g_edges[b + lane]);
        int   c = ev.x;
        float v = __int_as_float(ev.y);
#pragma unroll
        for (int j = 0; j < 32; j++) {
            int   cc = __shfl_sync(0xffffffffu, c, j);
            float vv = __shfl_sync(0xffffffffu, v, j);
            float4 xv = __ldg(src4 + (size_t)cc * 32 + lane);
            acc.x += vv * xv.x;
            acc.y += vv * xv.y;
            acc.z += vv * xv.z;
            acc.w += vv * xv.w;
        }
    }
    // tail
    int rem = end - b;
    if (rem > 0) {
        int2 ev = make_int2(0, 0);
        if (lane < rem) ev = __ldg(&g_edges[b + lane]);
        int   c = ev.x;
        float v = __int_as_float(ev.y);
#pragma unroll 4
        for (int j = 0; j < rem; j++) {
            int   cc = __shfl_sync(0xffffffffu, c, j);
            float vv = __shfl_sync(0xffffffffu, v, j);
            float4 xv = __ldg(src4 + (size_t)cc * 32 + lane);
            acc.x += vv * xv.x;
            acc.y += vv * xv.y;
            acc.z += vv * xv.z;
            acc.w += vv * xv.w;
        }
    }

    float4 o;
    if (beta != 0.f) {
        float4 p = __ldg((const float4*)prev + (size_t)row * 32 + lane);
        o.x = alpha * acc.x + beta * p.x;
        o.y = alpha * acc.y + beta * p.y;
        o.z = alpha * acc.z + beta * p.z;
        o.w = alpha * acc.w + beta * p.w;
    } else {
        o.x = alpha * acc.x;
        o.y = alpha * acc.y;
        o.z = alpha * acc.z;
        o.w = alpha * acc.w;
    }
    ((float4*)dst)[(size_t)row * 32 + lane] = o;
}

// ---------------------------------------------------------------------------
// Dense GEMM: out[n,o] = b[o] + sum_{t} sum_f Tt[n,f] * Wt[t][f][o]
// BM=128, BN=128, BK=16, 256 threads, 8x8 microtiles.
// ---------------------------------------------------------------------------
__global__ void __launch_bounds__(256) gemm_kernel(
    const float* __restrict__ x,
    const float* __restrict__ T1,
    const float* __restrict__ T2,
    const float* __restrict__ T3,
    const float* __restrict__ Wt,
    const float* __restrict__ bias,
    float*       __restrict__ out,
    int nRows)
{
    __shared__ float As[16][132];
    __shared__ float Ws[16][128];

    const int tid = threadIdx.x;
    const int m0  = blockIdx.x * 128;
    const int rm  = (tid >> 4) << 3;
    const int rn  = (tid & 15) << 3;

    float acc[8][8];
#pragma unroll
    for (int i = 0; i < 8; i++)
#pragma unroll
        for (int j = 0; j < 8; j++) acc[i][j] = 0.f;

    const float* srcs[4] = { x, T1, T2, T3 };

    for (int t = 0; t < 4; t++) {
        const float* A   = srcs[t];
        const float* Wtt = Wt + t * (F * F);
#pragma unroll 1
        for (int kc = 0; kc < 8; kc++) {
            __syncthreads();
#pragma unroll
            for (int rr = 0; rr < 2; rr++) {
                int mloc = (tid >> 2) + rr * 64;
                int m    = m0 + mloc;
                int f    = (kc << 4) + ((tid & 3) << 2);
                float4 va = make_float4(0.f, 0.f, 0.f, 0.f);
                if (m < nRows)
                    va = __ldg((const float4*)(A + (size_t)m * F + f));
                int fl = (tid & 3) << 2;
                As[fl + 0][mloc] = va.x;
                As[fl + 1][mloc] = va.y;
                As[fl + 2][mloc] = va.z;
                As[fl + 3][mloc] = va.w;
            }
#pragma unroll
            for (int rr = 0; rr < 2; rr++) {
                int idx = tid + rr * 256;
                int f   = idx >> 5;
                int o   = (idx & 31) << 2;
                *(float4*)&Ws[f][o] =
                    __ldg((const float4*)(Wtt + ((kc << 4) + f) * F + o));
            }
            __syncthreads();

#pragma unroll
            for (int kk = 0; kk < 16; kk++) {
                float4 a0 = *(const float4*)&As[kk][rm];
                float4 a1 = *(const float4*)&As[kk][rm + 4];
                float4 w0 = *(const float4*)&Ws[kk][rn];
                float4 w1 = *(const float4*)&Ws[kk][rn + 4];
                float a[8] = { a0.x, a0.y, a0.z, a0.w, a1.x, a1.y, a1.z, a1.w };
                float w[8] = { w0.x, w0.y, w0.z, w0.w, w1.x, w1.y, w1.z, w1.w };
#pragma unroll
                for (int i = 0; i < 8; i++)
#pragma unroll
                    for (int j = 0; j < 8; j++)
                        acc[i][j] += a[i] * w[j];
            }
        }
    }

    float4 b0 = __ldg((const float4*)(bias + rn));
    float4 b1 = __ldg((const float4*)(bias + rn + 4));
    float bb[8] = { b0.x, b0.y, b0.z, b0.w, b1.x, b1.y, b1.z, b1.w };

#pragma unroll
    for (int i = 0; i < 8; i++) {
        int m = m0 + rm + i;
        if (m < nRows) {
            float4 o0 = make_float4(acc[i][0] + bb[0], acc[i][1] + bb[1],
                                    acc[i][2] + bb[2], acc[i][3] + bb[3]);
            float4 o1 = make_float4(acc[i][4] + bb[4], acc[i][5] + bb[5],
                                    acc[i][6] + bb[6], acc[i][7] + bb[7]);
            *(float4*)(out + (size_t)m * F + rn)     = o0;
            *(float4*)(out + (size_t)m * F + rn + 4) = o1;
        }
    }
}

// ---------------------------------------------------------------------------
extern "C" void kernel_launch(void* const* d_in, const int* in_sizes, int n_in,
                              void* d_out, int out_size)
{
    const float* x    = (const float*)d_in[0];
    const int*   rows = (const int*)  d_in[1];
    const int*   cols = (const int*)  d_in[2];
    const float* vals = (const float*)d_in[3];
    const float* W    = (const float*)d_in[4];
    const float* b    = (const float*)d_in[5];
    float* out = (float*)d_out;

    int N = in_sizes[0] / F;
    int E = in_sizes[1];

    void *pT1, *pT2, *pT3, *pWt;
    cudaGetSymbolAddress(&pT1, g_T1);
    cudaGetSymbolAddress(&pT2, g_T2);
    cudaGetSymbolAddress(&pT3, g_T3);
    cudaGetSymbolAddress(&pWt, g_Wt);
    float* T1 = (float*)pT1;
    float* T2 = (float*)pT2;
    float* T3 = (float*)pT3;
    float* Wt = (float*)pWt;

    int nScanBlocks = (N + 1023) / 1024;
    int eBlocks = (E + 255) / 256;

    // ---- CSR build ----
    zero_hist_kernel<<<(N + 255) / 256, 256>>>(N);
    hist_kernel<<<eBlocks, 256>>>(rows, E);
    scan1_kernel<<<nScanBlocks, 1024>>>(N);
    scan2_kernel<<<1, 32>>>(nScanBlocks, E, N);
    scan3_kernel<<<nScanBlocks, 1024>>>(N);
    scatter_kernel<<<eBlocks, 256>>>(rows, cols, vals, E);

    // ---- W permute (overlaps CSR build on same stream order; cheap) ----
    prep_w_kernel<<<(4 * F * F + 255) / 256, 256>>>(W);

    // ---- Chebyshev recurrence via gather SpMM ----
    int spmmBlocks = (N * 32 + 255) / 256;   // warp per row
    // T1 = L x
    spmm_csr_kernel<<<spmmBlocks, 256>>>(x,  nullptr, T1, N, 1.0f,  0.0f);
    // T2 = 2 L T1 - x
    spmm_csr_kernel<<<spmmBlocks, 256>>>(T1, x,       T2, N, 2.0f, -1.0f);
    // T3 = 2 L T2 - T1
    spmm_csr_kernel<<<spmmBlocks, 256>>>(T2, T1,      T3, N, 2.0f, -1.0f);

    // ---- out = [x|T1|T2|T3] @ W^T + b ----
    int gblocks = (N + 127) / 128;
    gemm_kernel<<<gblocks, 256>>>(x, T1, T2, T3, Wt, b, out, N);
}

// round 3
// speedup vs baseline: 1.9636x; 1.1488x over previous
#include <cuda_runtime.h>
#include <cuda_fp16.h>
#include <cstdint>

#define F 128
#define NMAX 100000
#define EMAX 3200000

// ---------------------------------------------------------------------------
// Device scratch (no allocation allowed in kernel_launch)
// ---------------------------------------------------------------------------
__device__ float g_T1[(size_t)NMAX * F];
__device__ float g_T2[(size_t)NMAX * F];
__device__ float g_T3[(size_t)NMAX * F];
// fp16 shadow copies for the gather operand (uint2 = 4 halves, forces 8B align)
__device__ uint2 g_xh [(size_t)NMAX * F / 4];
__device__ uint2 g_T1h[(size_t)NMAX * F / 4];
__device__ uint2 g_T2h[(size_t)NMAX * F / 4];
__device__ float g_Wt[4 * F * F];          // Wt[k][f][o] = W[o][f*4+k]
__device__ int   g_hist[NMAX];
__device__ int   g_rowptr[NMAX + 1];
__device__ int   g_cursor[NMAX];
__device__ int2  g_edges[EMAX];            // row-sorted {col, val-as-int}
__device__ int   g_bsum[128];

// ---------------------------------------------------------------------------
// CSR build
// ---------------------------------------------------------------------------
__global__ void zero_hist_kernel(int n) {
    int i = blockIdx.x * blockDim.x + threadIdx.x;
    if (i < n) g_hist[i] = 0;
}

__global__ void hist_kernel(const int* __restrict__ rows, int nE) {
    int e = blockIdx.x * blockDim.x + threadIdx.x;
    if (e < nE) atomicAdd(&g_hist[rows[e]], 1);
}

__global__ void scan1_kernel(int n) {
    __shared__ int s[1024];
    int t = threadIdx.x;
    int i = blockIdx.x * 1024 + t;
    int cnt = (i < n) ? g_hist[i] : 0;
    s[t] = cnt;
    __syncthreads();
#pragma unroll
    for (int off = 1; off < 1024; off <<= 1) {
        int v = (t >= off) ? s[t - off] : 0;
        __syncthreads();
        s[t] += v;
        __syncthreads();
    }
    if (i < n) g_rowptr[i] = s[t] - cnt;   // exclusive
    if (t == 1023) g_bsum[blockIdx.x] = s[1023];
}

// parallel exclusive scan of <=128 block sums
__global__ void scan2_kernel(int nBlocks, int nE, int n) {
    __shared__ int s[128];
    int t = threadIdx.x;
    int v = (t < nBlocks) ? g_bsum[t] : 0;
    s[t] = v;
    __syncthreads();
#pragma unroll
    for (int off = 1; off < 128; off <<= 1) {
        int u = (t >= off) ? s[t - off] : 0;
        __syncthreads();
        s[t] += u;
        __syncthreads();
    }
    if (t < nBlocks) g_bsum[t] = s[t] - v;   // exclusive
    if (t == 0) g_rowptr[n] = nE;
}

__global__ void scan3_kernel(int n) {
    int i = blockIdx.x * 1024 + threadIdx.x;
    if (i < n) {
        int v = g_rowptr[i] + g_bsum[i >> 10];
        g_rowptr[i] = v;
        g_cursor[i] = v;
    }
}

__global__ void scatter_kernel(const int* __restrict__ rows,
                               const int* __restrict__ cols,
                               const float* __restrict__ vals, int nE) {
    int e = blockIdx.x * blockDim.x + threadIdx.x;
    if (e >= nE) return;
    int r = rows[e];
    int pos = atomicAdd(&g_cursor[r], 1);
    g_edges[pos] = make_int2(cols[e], __float_as_int(vals[e]));
}

// ---------------------------------------------------------------------------
// x -> fp16 shadow
// ---------------------------------------------------------------------------
__global__ void convert_x_kernel(const float4* __restrict__ x4, int n4) {
    int i = blockIdx.x * blockDim.x + threadIdx.x;
    if (i >= n4) return;
    float4 v = x4[i];
    __half2 h0 = __floats2half2_rn(v.x, v.y);
    __half2 h1 = __floats2half2_rn(v.z, v.w);
    uint2 u;
    u.x = *(unsigned*)&h0;
    u.y = *(unsigned*)&h1;
    g_xh[i] = u;
}

// ---------------------------------------------------------------------------
// W permutation: W is [128, 512] with inner index f*4+k -> Wt[k][f][o]
// ---------------------------------------------------------------------------
__global__ void prep_w_kernel(const float* __restrict__ W) {
    int idx = blockIdx.x * blockDim.x + threadIdx.x;
    if (idx >= 4 * F * F) return;
    int o = idx & 127;
    int f = (idx >> 7) & 127;
    int k = idx >> 14;
    g_Wt[k * F * F + f * F + o] = W[o * 512 + f * 4 + k];
}

// ---------------------------------------------------------------------------
// CSR SpMM, warp-per-row, fp16 gather, fp32 accumulate + epilogue.
// dst[r] = alpha * sum_e val[e]*srcH[col[e]]  +  beta * prev[r]
// Also writes fp16 shadow of dst (dstH) if non-null.
// ---------------------------------------------------------------------------
__device__ __forceinline__ void gather_fma(const uint2* __restrict__ srcH,
                                           int cc, float vv, int lane,
                                           float4& acc)
{
    uint2 u = __ldg(srcH + (size_t)cc * 32 + lane);
    __half2 h0 = *(__half2*)&u.x;
    __half2 h1 = *(__half2*)&u.y;
    float2 f0 = __half22float2(h0);
    float2 f1 = __half22float2(h1);
    acc.x = fmaf(vv, f0.x, acc.x);
    acc.y = fmaf(vv, f0.y, acc.y);
    acc.z = fmaf(vv, f1.x, acc.z);
    acc.w = fmaf(vv, f1.y, acc.w);
}

__global__ void __launch_bounds__(256) spmm_csr_h_kernel(
    const uint2* __restrict__ srcH,
    const float* __restrict__ prev,
    float*       __restrict__ dst,
    uint2*       __restrict__ dstH,
    int N, float alpha, float beta)
{
    int row  = (blockIdx.x * blockDim.x + threadIdx.x) >> 5;
    int lane = threadIdx.x & 31;
    if (row >= N) return;

    int start = __ldg(&g_rowptr[row]);
    int end   = __ldg(&g_rowptr[row + 1]);

    float4 acc = make_float4(0.f, 0.f, 0.f, 0.f);

    int b = start;
    for (; b + 32 <= end; b += 32) {
        int2 ev = __ldg(&g_edges[b + lane]);
        int   c = ev.x;
        float v = __int_as_float(ev.y);
#pragma unroll
        for (int j = 0; j < 32; j++) {
            int   cc = __shfl_sync(0xffffffffu, c, j);
            float vv = __shfl_sync(0xffffffffu, v, j);
            gather_fma(srcH, cc, vv, lane, acc);
        }
    }
    int rem = end - b;
    if (rem > 0) {
        int2 ev = make_int2(0, 0);
        if (lane < rem) ev = __ldg(&g_edges[b + lane]);
        int   c = ev.x;
        float v = __int_as_float(ev.y);
#pragma unroll 4
        for (int j = 0; j < rem; j++) {
            int   cc = __shfl_sync(0xffffffffu, c, j);
            float vv = __shfl_sync(0xffffffffu, v, j);
            gather_fma(srcH, cc, vv, lane, acc);
        }
    }

    float4 o;
    if (beta != 0.f) {
        float4 p = __ldg((const float4*)prev + (size_t)row * 32 + lane);
        o.x = fmaf(alpha, acc.x, beta * p.x);
        o.y = fmaf(alpha, acc.y, beta * p.y);
        o.z = fmaf(alpha, acc.z, beta * p.z);
        o.w = fmaf(alpha, acc.w, beta * p.w);
    } else {
        o.x = alpha * acc.x;
        o.y = alpha * acc.y;
        o.z = alpha * acc.z;
        o.w = alpha * acc.w;
    }
    ((float4*)dst)[(size_t)row * 32 + lane] = o;

    if (dstH) {
        __half2 h0 = __floats2half2_rn(o.x, o.y);
        __half2 h1 = __floats2half2_rn(o.z, o.w);
        uint2 u;
        u.x = *(unsigned*)&h0;
        u.y = *(unsigned*)&h1;
        dstH[(size_t)row * 32 + lane] = u;
    }
}

// ---------------------------------------------------------------------------
// Dense GEMM: out[n,o] = b[o] + sum_{t} sum_f Tt[n,f] * Wt[t][f][o]
// BM=128, BN=128, BK=16, 256 threads, 8x8 microtiles. (unchanged)
// ---------------------------------------------------------------------------
__global__ void __launch_bounds__(256) gemm_kernel(
    const float* __restrict__ x,
    const float* __restrict__ T1,
    const float* __restrict__ T2,
    const float* __restrict__ T3,
    const float* __restrict__ Wt,
    const float* __restrict__ bias,
    float*       __restrict__ out,
    int nRows)
{
    __shared__ float As[16][132];
    __shared__ float Ws[16][128];

    const int tid = threadIdx.x;
    const int m0  = blockIdx.x * 128;
    const int rm  = (tid >> 4) << 3;
    const int rn  = (tid & 15) << 3;

    float acc[8][8];
#pragma unroll
    for (int i = 0; i < 8; i++)
#pragma unroll
        for (int j = 0; j < 8; j++) acc[i][j] = 0.f;

    const float* srcs[4] = { x, T1, T2, T3 };

    for (int t = 0; t < 4; t++) {
        const float* A   = srcs[t];
        const float* Wtt = Wt + t * (F * F);
#pragma unroll 1
        for (int kc = 0; kc < 8; kc++) {
            __syncthreads();
#pragma unroll
            for (int rr = 0; rr < 2; rr++) {
                int mloc = (tid >> 2) + rr * 64;
                int m    = m0 + mloc;
                int f    = (kc << 4) + ((tid & 3) << 2);
                float4 va = make_float4(0.f, 0.f, 0.f, 0.f);
                if (m < nRows)
                    va = __ldg((const float4*)(A + (size_t)m * F + f));
                int fl = (tid & 3) << 2;
                As[fl + 0][mloc] = va.x;
                As[fl + 1][mloc] = va.y;
                As[fl + 2][mloc] = va.z;
                As[fl + 3][mloc] = va.w;
            }
#pragma unroll
            for (int rr = 0; rr < 2; rr++) {
                int idx = tid + rr * 256;
                int f   = idx >> 5;
                int o   = (idx & 31) << 2;
                *(float4*)&Ws[f][o] =
                    __ldg((const float4*)(Wtt + ((kc << 4) + f) * F + o));
            }
            __syncthreads();

#pragma unroll
            for (int kk = 0; kk < 16; kk++) {
                float4 a0 = *(const float4*)&As[kk][rm];
                float4 a1 = *(const float4*)&As[kk][rm + 4];
                float4 w0 = *(const float4*)&Ws[kk][rn];
                float4 w1 = *(const float4*)&Ws[kk][rn + 4];
                float a[8] = { a0.x, a0.y, a0.z, a0.w, a1.x, a1.y, a1.z, a1.w };
                float w[8] = { w0.x, w0.y, w0.z, w0.w, w1.x, w1.y, w1.z, w1.w };
#pragma unroll
                for (int i = 0; i < 8; i++)
#pragma unroll
                    for (int j = 0; j < 8; j++)
                        acc[i][j] += a[i] * w[j];
            }
        }
    }

    float4 b0 = __ldg((const float4*)(bias + rn));
    float4 b1 = __ldg((const float4*)(bias + rn + 4));
    float bb[8] = { b0.x, b0.y, b0.z, b0.w, b1.x, b1.y, b1.z, b1.w };

#pragma unroll
    for (int i = 0; i < 8; i++) {
        int m = m0 + rm + i;
        if (m < nRows) {
            float4 o0 = make_float4(acc[i][0] + bb[0], acc[i][1] + bb[1],
                                    acc[i][2] + bb[2], acc[i][3] + bb[3]);
            float4 o1 = make_float4(acc[i][4] + bb[4], acc[i][5] + bb[5],
                                    acc[i][6] + bb[6], acc[i][7] + bb[7]);
            *(float4*)(out + (size_t)m * F + rn)     = o0;
            *(float4*)(out + (size_t)m * F + rn + 4) = o1;
        }
    }
}

// ---------------------------------------------------------------------------
extern "C" void kernel_launch(void* const* d_in, const int* in_sizes, int n_in,
                              void* d_out, int out_size)
{
    const float* x    = (const float*)d_in[0];
    const int*   rows = (const int*)  d_in[1];
    const int*   cols = (const int*)  d_in[2];
    const float* vals = (const float*)d_in[3];
    const float* W    = (const float*)d_in[4];
    const float* b    = (const float*)d_in[5];
    float* out = (float*)d_out;

    int N = in_sizes[0] / F;
    int E = in_sizes[1];

    void *pT1, *pT2, *pT3, *pWt, *pXh, *pT1h, *pT2h;
    cudaGetSymbolAddress(&pT1, g_T1);
    cudaGetSymbolAddress(&pT2, g_T2);
    cudaGetSymbolAddress(&pT3, g_T3);
    cudaGetSymbolAddress(&pWt, g_Wt);
    cudaGetSymbolAddress(&pXh, g_xh);
    cudaGetSymbolAddress(&pT1h, g_T1h);
    cudaGetSymbolAddress(&pT2h, g_T2h);
    float* T1 = (float*)pT1;
    float* T2 = (float*)pT2;
    float* T3 = (float*)pT3;
    float* Wt = (float*)pWt;
    uint2* xh  = (uint2*)pXh;
    uint2* T1h = (uint2*)pT1h;
    uint2* T2h = (uint2*)pT2h;

    int nScanBlocks = (N + 1023) / 1024;
    int eBlocks = (E + 255) / 256;
    int n4 = (N * F) / 4;

    // ---- CSR build ----
    zero_hist_kernel<<<(N + 255) / 256, 256>>>(N);
    hist_kernel<<<eBlocks, 256>>>(rows, E);
    scan1_kernel<<<nScanBlocks, 1024>>>(N);
    scan2_kernel<<<1, 128>>>(nScanBlocks, E, N);
    scan3_kernel<<<nScanBlocks, 1024>>>(N);
    scatter_kernel<<<eBlocks, 256>>>(rows, cols, vals, E);

    // ---- prep: W permute + fp16 shadow of x ----
    prep_w_kernel<<<(4 * F * F + 255) / 256, 256>>>(W);
    convert_x_kernel<<<(n4 + 255) / 256, 256>>>((const float4*)x, n4);

    // ---- Chebyshev recurrence via fp16-gather SpMM ----
    int spmmBlocks = (N * 32 + 255) / 256;   // warp per row
    // T1 = L x
    spmm_csr_h_kernel<<<spmmBlocks, 256>>>(xh,  nullptr, T1, T1h, N, 1.0f,  0.0f);
    // T2 = 2 L T1 - x
    spmm_csr_h_kernel<<<spmmBlocks, 256>>>(T1h, x,       T2, T2h, N, 2.0f, -1.0f);
    // T3 = 2 L T2 - T1
    spmm_csr_h_kernel<<<spmmBlocks, 256>>>(T2h, T1,      T3, nullptr, N, 2.0f, -1.0f);

    // ---- out = [x|T1|T2|T3] @ W^T + b ----
    int gblocks = (N + 127) / 128;
    gemm_kernel<<<gblocks, 256>>>(x, T1, T2, T3, Wt, b, out, N);
}

// round 5
// speedup vs baseline: 3.3675x; 1.7150x over previous
#include <cuda_runtime.h>
#include <cuda_fp16.h>
#include <cstdint>

#define F 128
#define NMAX 100000
#define EMAX 3200000

// ---------------------------------------------------------------------------
// Device scratch — all cheb feature matrices live in fp16 only.
// uint4 type guarantees 16B alignment for vectorized access.
// ---------------------------------------------------------------------------
__device__ uint4  g_xh [(size_t)NMAX * F / 8];
__device__ uint4  g_T1h[(size_t)NMAX * F / 8];
__device__ uint4  g_T2h[(size_t)NMAX * F / 8];
__device__ uint4  g_T3h[(size_t)NMAX * F / 8];
__device__ __half g_Wh[4 * F * F];         // Wh[k][o], k = t*128 + f
__device__ int    g_hist[NMAX];
__device__ int    g_rowptr[NMAX + 1];
__device__ int    g_cursor[NMAX];
__device__ int2   g_edges[EMAX];           // row-sorted {col, val-as-int}
__device__ int    g_bsum[128];

// ---------------------------------------------------------------------------
// CSR build
// ---------------------------------------------------------------------------
__global__ void zero_hist_kernel(int n) {
    int i = blockIdx.x * blockDim.x + threadIdx.x;
    if (i < n) g_hist[i] = 0;
}

__global__ void hist_kernel(const int* __restrict__ rows, int nE) {
    int e = blockIdx.x * blockDim.x + threadIdx.x;
    if (e < nE) atomicAdd(&g_hist[rows[e]], 1);
}

__global__ void scan1_kernel(int n) {
    __shared__ int s[1024];
    int t = threadIdx.x;
    int i = blockIdx.x * 1024 + t;
    int cnt = (i < n) ? g_hist[i] : 0;
    s[t] = cnt;
    __syncthreads();
#pragma unroll
    for (int off = 1; off < 1024; off <<= 1) {
        int v = (t >= off) ? s[t - off] : 0;
        __syncthreads();
        s[t] += v;
        __syncthreads();
    }
    if (i < n) g_rowptr[i] = s[t] - cnt;
    if (t == 1023) g_bsum[blockIdx.x] = s[1023];
}

__global__ void scan2_kernel(int nBlocks, int nE, int n) {
    __shared__ int s[128];
    int t = threadIdx.x;
    int v = (t < nBlocks) ? g_bsum[t] : 0;
    s[t] = v;
    __syncthreads();
#pragma unroll
    for (int off = 1; off < 128; off <<= 1) {
        int u = (t >= off) ? s[t - off] : 0;
        __syncthreads();
        s[t] += u;
        __syncthreads();
    }
    if (t < nBlocks) g_bsum[t] = s[t] - v;
    if (t == 0) g_rowptr[n] = nE;
}

__global__ void scan3_kernel(int n) {
    int i = blockIdx.x * 1024 + threadIdx.x;
    if (i < n) {
        int v = g_rowptr[i] + g_bsum[i >> 10];
        g_rowptr[i] = v;
        g_cursor[i] = v;
    }
}

__global__ void scatter_kernel(const int* __restrict__ rows,
                               const int* __restrict__ cols,
                               const float* __restrict__ vals, int nE) {
    int e = blockIdx.x * blockDim.x + threadIdx.x;
    if (e >= nE) return;
    int r = rows[e];
    int pos = atomicAdd(&g_cursor[r], 1);
    g_edges[pos] = make_int2(cols[e], __float_as_int(vals[e]));
}

// ---------------------------------------------------------------------------
// x -> fp16
// ---------------------------------------------------------------------------
__global__ void convert_x_kernel(const float4* __restrict__ x4, int n4) {
    int i = blockIdx.x * blockDim.x + threadIdx.x;
    if (i >= n4) return;
    float4 v = x4[i];
    __half2 h0 = __floats2half2_rn(v.x, v.y);
    __half2 h1 = __floats2half2_rn(v.z, v.w);
    uint2 u;
    u.x = *(unsigned*)&h0;
    u.y = *(unsigned*)&h1;
    ((uint2*)g_xh)[i] = u;
}

// ---------------------------------------------------------------------------
// W [128,512] inner index f*4+t  ->  Wh[(t*128+f)*128 + o]  (fp16)
// ---------------------------------------------------------------------------
__global__ void prep_w_kernel(const float* __restrict__ W) {
    int idx = blockIdx.x * blockDim.x + threadIdx.x;
    if (idx >= 4 * F * F) return;
    int o = idx & 127;
    int f = (idx >> 7) & 127;
    int t = idx >> 14;
    g_Wh[(t * 128 + f) * 128 + o] = __float2half_rn(W[o * 512 + f * 4 + t]);
}

// ---------------------------------------------------------------------------
// CSR SpMM, warp-per-row, fp16 gather + fp16 prev, fp32 accumulate.
// dstH[r] = fp16( alpha * sum_e val[e]*srcH[col[e]]  +  beta * prevH[r] )
// ---------------------------------------------------------------------------
__device__ __forceinline__ void gather_fma(const uint2* __restrict__ srcH,
                                           int cc, float vv, int lane,
                                           float4& acc)
{
    uint2 u = __ldg(srcH + (size_t)cc * 32 + lane);
    __half2 h0 = *(__half2*)&u.x;
    __half2 h1 = *(__half2*)&u.y;
    float2 f0 = __half22float2(h0);
    float2 f1 = __half22float2(h1);
    acc.x = fmaf(vv, f0.x, acc.x);
    acc.y = fmaf(vv, f0.y, acc.y);
    acc.z = fmaf(vv, f1.x, acc.z);
    acc.w = fmaf(vv, f1.y, acc.w);
}

__global__ void __launch_bounds__(256) spmm_csr_h_kernel(
    const uint2* __restrict__ srcH,
    const uint2* __restrict__ prevH,
    uint2*       __restrict__ dstH,
    int N, float alpha, float beta)
{
    int row  = (blockIdx.x * blockDim.x + threadIdx.x) >> 5;
    int lane = threadIdx.x & 31;
    if (row >= N) return;

    int start = __ldg(&g_rowptr[row]);
    int end   = __ldg(&g_rowptr[row + 1]);

    float4 acc = make_float4(0.f, 0.f, 0.f, 0.f);

    int b = start;
    for (; b + 32 <= end; b += 32) {
        int2 ev = __ldg(&g_edges[b + lane]);
        int   c = ev.x;
        float v = __int_as_float(ev.y);
#pragma unroll
        for (int j = 0; j < 32; j++) {
            int   cc = __shfl_sync(0xffffffffu, c, j);
            float vv = __shfl_sync(0xffffffffu, v, j);
            gather_fma(srcH, cc, vv, lane, acc);
        }
    }
    int rem = end - b;
    if (rem > 0) {
        int2 ev = make_int2(0, 0);
        if (lane < rem) ev = __ldg(&g_edges[b + lane]);
        int   c = ev.x;
        float v = __int_as_float(ev.y);
#pragma unroll 4
        for (int j = 0; j < rem; j++) {
            int   cc = __shfl_sync(0xffffffffu, c, j);
            float vv = __shfl_sync(0xffffffffu, v, j);
            gather_fma(srcH, cc, vv, lane, acc);
        }
    }

    float4 o;
    if (beta != 0.f) {
        uint2 up = __ldg(prevH + (size_t)row * 32 + lane);
        float2 p0 = __half22float2(*(__half2*)&up.x);
        float2 p1 = __half22float2(*(__half2*)&up.y);
        o.x = fmaf(alpha, acc.x, beta * p0.x);
        o.y = fmaf(alpha, acc.y, beta * p0.y);
        o.z = fmaf(alpha, acc.z, beta * p1.x);
        o.w = fmaf(alpha, acc.w, beta * p1.y);
    } else {
        o.x = alpha * acc.x;
        o.y = alpha * acc.y;
        o.z = alpha * acc.z;
        o.w = alpha * acc.w;
    }
    __half2 h0 = __floats2half2_rn(o.x, o.y);
    __half2 h1 = __floats2half2_rn(o.z, o.w);
    uint2 u;
    u.x = *(unsigned*)&h0;
    u.y = *(unsigned*)&h1;
    dstH[(size_t)row * 32 + lane] = u;
}

// ---------------------------------------------------------------------------
// Tensor-core GEMM (fp16 in, fp32 acc):
//   out[m,o] = bias[o] + sum_{k=0..511} A[m,k] * Wh[k,o]
//   A = [xh | T1h | T2h | T3h] concatenated along k.
// BM=128, BN=128, BK=32; 8 warps (4 m x 2 n); warp tile 32x64;
// mma.sync.m16n8k16 + ldmatrix.
// ---------------------------------------------------------------------------
__device__ __forceinline__ void ldsm_x4(uint32_t& r0, uint32_t& r1,
                                        uint32_t& r2, uint32_t& r3,
                                        uint32_t addr) {
    asm volatile("ldmatrix.sync.aligned.m8n8.x4.shared.b16 {%0,%1,%2,%3}, [%4];"
                 : "=r"(r0), "=r"(r1), "=r"(r2), "=r"(r3) : "r"(addr));
}
__device__ __forceinline__ void ldsm_x4_t(uint32_t& r0, uint32_t& r1,
                                          uint32_t& r2, uint32_t& r3,
                                          uint32_t addr) {
    asm volatile("ldmatrix.sync.aligned.m8n8.x4.trans.shared.b16 {%0,%1,%2,%3}, [%4];"
                 : "=r"(r0), "=r"(r1), "=r"(r2), "=r"(r3) : "r"(addr));
}
__device__ __forceinline__ void mma16816(float* c, const uint32_t* a,
                                         uint32_t b0, uint32_t b1) {
    asm volatile(
        "mma.sync.aligned.m16n8k16.row.col.f32.f16.f16.f32 "
        "{%0,%1,%2,%3}, {%4,%5,%6,%7}, {%8,%9}, {%0,%1,%2,%3};"
        : "+f"(c[0]), "+f"(c[1]), "+f"(c[2]), "+f"(c[3])
        : "r"(a[0]), "r"(a[1]), "r"(a[2]), "r"(a[3]), "r"(b0), "r"(b1));
}

__global__ void __launch_bounds__(256) gemm_h_kernel(
    const uint4* __restrict__ A0, const uint4* __restrict__ A1,
    const uint4* __restrict__ A2, const uint4* __restrict__ A3,
    const __half* __restrict__ Wh, const float* __restrict__ bias,
    float* __restrict__ out, int N)
{
    __shared__ __align__(16) __half As[128 * 40];   // [m][k], stride 40
    __shared__ __align__(16) __half Bs[32 * 136];   // [k][o], stride 136

    const int tid  = threadIdx.x;
    const int lane = tid & 31;
    const int wid  = tid >> 5;
    const int m0   = blockIdx.x * 128;
    const int mbase = (wid & 3) * 32;
    const int nbase = (wid >> 2) * 64;
    const int lt = lane >> 3;        // ldmatrix tile index
    const int lr = lane & 7;         // ldmatrix row-in-tile

    const uint4* srcs[4] = { A0, A1, A2, A3 };

    float acc[2][8][4];
#pragma unroll
    for (int mt = 0; mt < 2; mt++)
#pragma unroll
        for (int nt = 0; nt < 8; nt++)
#pragma unroll
            for (int i = 0; i < 4; i++) acc[mt][nt][i] = 0.f;

    uint32_t as_base = (uint32_t)__cvta_generic_to_shared(As);
    uint32_t bs_base = (uint32_t)__cvta_generic_to_shared(Bs);

#pragma unroll 1
    for (int kc = 0; kc < 16; kc++) {
        const uint4* Asrc = srcs[kc >> 2];
        int f4 = (kc & 3) * 4;                     // uint4 offset within row
        __syncthreads();
        // A tile: 128 rows x 32 halves = 512 uint4 slots
#pragma unroll
        for (int s = 0; s < 2; s++) {
            int slot = tid * 2 + s;
            int r = slot >> 2, c4 = slot & 3;
            uint4 v = make_uint4(0, 0, 0, 0);
            if (m0 + r < N) v = __ldg(Asrc + (size_t)(m0 + r) * 16 + f4 + c4);
            *(uint4*)(As + r * 40 + c4 * 8) = v;
        }
        // B tile: 32 rows x 128 halves = 512 uint4 slots
#pragma unroll
        for (int s = 0; s < 2; s++) {
            int slot = tid * 2 + s;
            int r = slot >> 4, c4 = slot & 15;
            uint4 v = *(const uint4*)(Wh + (size_t)(kc * 32 + r) * 128 + c4 * 8);
            *(uint4*)(Bs + r * 136 + c4 * 8) = v;
        }
        __syncthreads();

#pragma unroll
        for (int kk = 0; kk < 32; kk += 16) {
            uint32_t a[2][4];
#pragma unroll
            for (int mt = 0; mt < 2; mt++) {
                int arow = mbase + mt * 16 + (lt & 1) * 8 + lr;
                int acol = kk + (lt >> 1) * 8;
                ldsm_x4(a[mt][0], a[mt][1], a[mt][2], a[mt][3],
                        as_base + 2u * (arow * 40 + acol));
            }
            uint32_t bfr[4][4];
#pragma unroll
            for (int n2 = 0; n2 < 4; n2++) {
                int brow = kk + (lt & 1) * 8 + lr;
                int bcol = nbase + n2 * 16 + (lt >> 1) * 8;
                ldsm_x4_t(bfr[n2][0], bfr[n2][1], bfr[n2][2], bfr[n2][3],
                          bs_base + 2u * (brow * 136 + bcol));
            }
#pragma unroll
            for (int mt = 0; mt < 2; mt++)
#pragma unroll
                for (int nt = 0; nt < 8; nt++) {
                    int n2 = nt >> 1, p = (nt & 1) * 2;
                    mma16816(acc[mt][nt], a[mt], bfr[n2][p], bfr[n2][p + 1]);
                }
        }
    }

    // epilogue
#pragma unroll
    for (int nt = 0; nt < 8; nt++) {
        int col = nbase + nt * 8 + (lane & 3) * 2;
        float2 bv = *(const float2*)(bias + col);
#pragma unroll
        for (int mt = 0; mt < 2; mt++) {
            int r0 = m0 + mbase + mt * 16 + (lane >> 2);
            if (r0 < N) {
                float2 o0 = make_float2(acc[mt][nt][0] + bv.x,
                                        acc[mt][nt][1] + bv.y);
                *(float2*)(out + (size_t)r0 * 128 + col) = o0;
            }
            int r1 = r0 + 8;
            if (r1 < N) {
                float2 o1 = make_float2(acc[mt][nt][2] + bv.x,
                                        acc[mt][nt][3] + bv.y);
                *(float2*)(out + (size_t)r1 * 128 + col) = o1;
            }
        }
    }
}

// ---------------------------------------------------------------------------
extern "C" void kernel_launch(void* const* d_in, const int* in_sizes, int n_in,
                              void* d_out, int out_size)
{
    const float* x    = (const float*)d_in[0];
    const int*   rows = (const int*)  d_in[1];
    const int*   cols = (const int*)  d_in[2];
    const float* vals = (const float*)d_in[3];
    const float* W    = (const float*)d_in[4];
    const float* b    = (const float*)d_in[5];
    float* out = (float*)d_out;

    int N = in_sizes[0] / F;
    int E = in_sizes[1];

    void *pXh, *pT1h, *pT2h, *pT3h, *pWh;
    cudaGetSymbolAddress(&pXh,  g_xh);
    cudaGetSymbolAddress(&pT1h, g_T1h);
    cudaGetSymbolAddress(&pT2h, g_T2h);
    cudaGetSymbolAddress(&pT3h, g_T3h);
    cudaGetSymbolAddress(&pWh,  g_Wh);
    uint4* xh  = (uint4*)pXh;
    uint4* T1h = (uint4*)pT1h;
    uint4* T2h = (uint4*)pT2h;
    uint4* T3h = (uint4*)pT3h;
    __half* Wh = (__half*)pWh;

    int nScanBlocks = (N + 1023) / 1024;
    int eBlocks = (E + 255) / 256;
    int n4 = (N * F) / 4;

    // ---- CSR build ----
    zero_hist_kernel<<<(N + 255) / 256, 256>>>(N);
    hist_kernel<<<eBlocks, 256>>>(rows, E);
    scan1_kernel<<<nScanBlocks, 1024>>>(N);
    scan2_kernel<<<1, 128>>>(nScanBlocks, E, N);
    scan3_kernel<<<nScanBlocks, 1024>>>(N);
    scatter_kernel<<<eBlocks, 256>>>(rows, cols, vals, E);

    // ---- prep ----
    prep_w_kernel<<<(4 * F * F + 255) / 256, 256>>>(W);
    convert_x_kernel<<<(n4 + 255) / 256, 256>>>((const float4*)x, n4);

    // ---- Chebyshev recurrence (all fp16 storage, fp32 math) ----
    int spmmBlocks = (N * 32 + 255) / 256;
    // T1 = L x
    spmm_csr_h_kernel<<<spmmBlocks, 256>>>((const uint2*)xh,  nullptr,
                                           (uint2*)T1h, N, 1.0f,  0.0f);
    // T2 = 2 L T1 - x
    spmm_csr_h_kernel<<<spmmBlocks, 256>>>((const uint2*)T1h, (const uint2*)xh,
                                           (uint2*)T2h, N, 2.0f, -1.0f);
    // T3 = 2 L T2 - T1
    spmm_csr_h_kernel<<<spmmBlocks, 256>>>((const uint2*)T2h, (const uint2*)T1h,
                                           (uint2*)T3h, N, 2.0f, -1.0f);

    // ---- out = [x|T1|T2|T3] @ W^T + b  (tensor cores) ----
    int gblocks = (N + 127) / 128;
    gemm_h_kernel<<<gblocks, 256>>>(xh, T1h, T2h, T3h, Wh, b, out, N);
}

// round 6
// speedup vs baseline: 3.4666x; 1.0294x over previous
#include <cuda_runtime.h>
#include <cuda_fp16.h>
#include <cstdint>

#define F 128
#define NMAX 100000
#define EMAX 3200000

// ---------------------------------------------------------------------------
// Device scratch — all cheb feature matrices live in fp16 only.
// ---------------------------------------------------------------------------
__device__ uint4  g_xh [(size_t)NMAX * F / 8];
__device__ uint4  g_T1h[(size_t)NMAX * F / 8];
__device__ uint4  g_T2h[(size_t)NMAX * F / 8];
__device__ uint4  g_T3h[(size_t)NMAX * F / 8];
__device__ __half g_Wh[4 * F * F];         // Wh[k][o], k = t*128 + f
__device__ int    g_hist[NMAX];
__device__ int    g_rowptr[NMAX + 1];
__device__ int    g_cursor[NMAX];
__device__ int2   g_edges[EMAX];           // row-sorted {col, val-as-int}
__device__ int    g_bsum[128];

// ---------------------------------------------------------------------------
// Fused prep: zero hist + x->fp16 + W permute/convert.
// Grid covers n4 = N*F/4 elements (largest of the three jobs).
// ---------------------------------------------------------------------------
__global__ void prep_kernel(const float4* __restrict__ x4, int n4, int n,
                            const float* __restrict__ W) {
    int i = blockIdx.x * blockDim.x + threadIdx.x;
    if (i < n) g_hist[i] = 0;
    if (i < 4 * F * F) {
        int o = i & 127;
        int f = (i >> 7) & 127;
        int t = i >> 14;
        g_Wh[(t * 128 + f) * 128 + o] = __float2half_rn(W[o * 512 + f * 4 + t]);
    }
    if (i < n4) {
        float4 v = x4[i];
        __half2 h0 = __floats2half2_rn(v.x, v.y);
        __half2 h1 = __floats2half2_rn(v.z, v.w);
        uint2 u;
        u.x = *(unsigned*)&h0;
        u.y = *(unsigned*)&h1;
        ((uint2*)g_xh)[i] = u;
    }
}

// ---------------------------------------------------------------------------
// CSR build
// ---------------------------------------------------------------------------
__global__ void hist_kernel(const int* __restrict__ rows, int nE) {
    int e = blockIdx.x * blockDim.x + threadIdx.x;
    if (e < nE) atomicAdd(&g_hist[rows[e]], 1);
}

__global__ void scan1_kernel(int n) {
    __shared__ int s[1024];
    int t = threadIdx.x;
    int i = blockIdx.x * 1024 + t;
    int cnt = (i < n) ? g_hist[i] : 0;
    s[t] = cnt;
    __syncthreads();
#pragma unroll
    for (int off = 1; off < 1024; off <<= 1) {
        int v = (t >= off) ? s[t - off] : 0;
        __syncthreads();
        s[t] += v;
        __syncthreads();
    }
    if (i < n) g_rowptr[i] = s[t] - cnt;   // block-local exclusive
    if (t == 1023) g_bsum[blockIdx.x] = s[1023];
}

// finalize: every block computes its own prefix of the (<=128) block sums,
// then applies the offset. Kills the separate single-block scan launch.
__global__ void scan_finalize_kernel(int n, int nBlocks, int nE) {
    __shared__ int s[128];
    int t = threadIdx.x;
    int bid = blockIdx.x;
    if (t < 128) {
        s[t] = (t < nBlocks && t < bid) ? g_bsum[t] : 0;
    }
    __syncthreads();
    if (t < 64) s[t] += s[t + 64];
    __syncthreads();
    if (t < 32) {
        int v = s[t] + s[t + 32];
#pragma unroll
        for (int off = 16; off > 0; off >>= 1)
            v += __shfl_down_sync(0xffffffffu, v, off);
        if (t == 0) s[0] = v;
    }
    __syncthreads();
    int offset = s[0];
    int i = bid * 1024 + t;
    if (i < n) {
        int v = g_rowptr[i] + offset;
        g_rowptr[i] = v;
        g_cursor[i] = v;
    }
    if (bid == 0 && t == 0) g_rowptr[n] = nE;
}

__global__ void scatter_kernel(const int* __restrict__ rows,
                               const int* __restrict__ cols,
                               const float* __restrict__ vals, int nE) {
    int e = blockIdx.x * blockDim.x + threadIdx.x;
    if (e >= nE) return;
    int r = rows[e];
    int pos = atomicAdd(&g_cursor[r], 1);
    g_edges[pos] = make_int2(cols[e], __float_as_int(vals[e]));
}

// ---------------------------------------------------------------------------
// CSR SpMM, warp-per-row, fp16 gather + fp16 prev, fp32 accumulate.
// dstH[r] = fp16( alpha * sum_e val[e]*srcH[col[e]]  +  beta * prevH[r] )
// ---------------------------------------------------------------------------
__device__ __forceinline__ void gather_fma(const uint2* __restrict__ srcH,
                                           int cc, float vv, int lane,
                                           float4& acc)
{
    uint2 u = __ldg(srcH + (size_t)cc * 32 + lane);
    __half2 h0 = *(__half2*)&u.x;
    __half2 h1 = *(__half2*)&u.y;
    float2 f0 = __half22float2(h0);
    float2 f1 = __half22float2(h1);
    acc.x = fmaf(vv, f0.x, acc.x);
    acc.y = fmaf(vv, f0.y, acc.y);
    acc.z = fmaf(vv, f1.x, acc.z);
    acc.w = fmaf(vv, f1.y, acc.w);
}

__global__ void __launch_bounds__(256) spmm_csr_h_kernel(
    const uint2* __restrict__ srcH,
    const uint2* __restrict__ prevH,
    uint2*       __restrict__ dstH,
    int N, float alpha, float beta)
{
    int row  = (blockIdx.x * blockDim.x + threadIdx.x) >> 5;
    int lane = threadIdx.x & 31;
    if (row >= N) return;

    int start = __ldg(&g_rowptr[row]);
    int end   = __ldg(&g_rowptr[row + 1]);

    float4 acc = make_float4(0.f, 0.f, 0.f, 0.f);

    int b = start;
    for (; b + 32 <= end; b += 32) {
        int2 ev = __ldg(&g_edges[b + lane]);
        int   c = ev.x;
        float v = __int_as_float(ev.y);
#pragma unroll
        for (int j = 0; j < 32; j++) {
            int   cc = __shfl_sync(0xffffffffu, c, j);
            float vv = __shfl_sync(0xffffffffu, v, j);
            gather_fma(srcH, cc, vv, lane, acc);
        }
    }
    int rem = end - b;
    if (rem > 0) {
        int2 ev = make_int2(0, 0);
        if (lane < rem) ev = __ldg(&g_edges[b + lane]);
        int   c = ev.x;
        float v = __int_as_float(ev.y);
#pragma unroll 4
        for (int j = 0; j < rem; j++) {
            int   cc = __shfl_sync(0xffffffffu, c, j);
            float vv = __shfl_sync(0xffffffffu, v, j);
            gather_fma(srcH, cc, vv, lane, acc);
        }
    }

    float4 o;
    if (beta != 0.f) {
        uint2 up = __ldg(prevH + (size_t)row * 32 + lane);
        float2 p0 = __half22float2(*(__half2*)&up.x);
        float2 p1 = __half22float2(*(__half2*)&up.y);
        o.x = fmaf(alpha, acc.x, beta * p0.x);
        o.y = fmaf(alpha, acc.y, beta * p0.y);
        o.z = fmaf(alpha, acc.z, beta * p1.x);
        o.w = fmaf(alpha, acc.w, beta * p1.y);
    } else {
        o.x = alpha * acc.x;
        o.y = alpha * acc.y;
        o.z = alpha * acc.z;
        o.w = alpha * acc.w;
    }
    __half2 h0 = __floats2half2_rn(o.x, o.y);
    __half2 h1 = __floats2half2_rn(o.z, o.w);
    uint2 u;
    u.x = *(unsigned*)&h0;
    u.y = *(unsigned*)&h1;
    dstH[(size_t)row * 32 + lane] = u;
}

// ---------------------------------------------------------------------------
// Tensor-core GEMM (fp16 in, fp32 acc), cp.async double-buffered.
//   out[m,o] = bias[o] + sum_{k=0..511} A[m,k] * Wh[k,o]
// BM=128, BN=128, BK=32; 8 warps (4 m x 2 n); mma.sync.m16n8k16.
// ---------------------------------------------------------------------------
__device__ __forceinline__ void ldsm_x4(uint32_t& r0, uint32_t& r1,
                                        uint32_t& r2, uint32_t& r3,
                                        uint32_t addr) {
    asm volatile("ldmatrix.sync.aligned.m8n8.x4.shared.b16 {%0,%1,%2,%3}, [%4];"
                 : "=r"(r0), "=r"(r1), "=r"(r2), "=r"(r3) : "r"(addr));
}
__device__ __forceinline__ void ldsm_x4_t(uint32_t& r0, uint32_t& r1,
                                          uint32_t& r2, uint32_t& r3,
                                          uint32_t addr) {
    asm volatile("ldmatrix.sync.aligned.m8n8.x4.trans.shared.b16 {%0,%1,%2,%3}, [%4];"
                 : "=r"(r0), "=r"(r1), "=r"(r2), "=r"(r3) : "r"(addr));
}
__device__ __forceinline__ void mma16816(float* c, const uint32_t* a,
                                         uint32_t b0, uint32_t b1) {
    asm volatile(
        "mma.sync.aligned.m16n8k16.row.col.f32.f16.f16.f32 "
        "{%0,%1,%2,%3}, {%4,%5,%6,%7}, {%8,%9}, {%0,%1,%2,%3};"
        : "+f"(c[0]), "+f"(c[1]), "+f"(c[2]), "+f"(c[3])
        : "r"(a[0]), "r"(a[1]), "r"(a[2]), "r"(a[3]), "r"(b0), "r"(b1));
}

#define CP_ASYNC16(dst, src, sz) \
    asm volatile("cp.async.cg.shared.global [%0], [%1], 16, %2;" \
                 :: "r"(dst), "l"(src), "r"(sz))
#define CP_COMMIT() asm volatile("cp.async.commit_group;")
#define CP_WAIT0()  asm volatile("cp.async.wait_group 0;")

#define AS_STRIDE 40
#define BS_STRIDE 136
#define AS_BYTES  (128 * AS_STRIDE * 2)
#define BS_BYTES  (32 * BS_STRIDE * 2)

__global__ void __launch_bounds__(256) gemm_h_kernel(
    const uint4* __restrict__ A0, const uint4* __restrict__ A1,
    const uint4* __restrict__ A2, const uint4* __restrict__ A3,
    const __half* __restrict__ Wh, const float* __restrict__ bias,
    float* __restrict__ out, int N)
{
    __shared__ __align__(16) __half As[2][128 * AS_STRIDE];
    __shared__ __align__(16) __half Bs[2][32 * BS_STRIDE];

    const int tid  = threadIdx.x;
    const int lane = tid & 31;
    const int wid  = tid >> 5;
    const int m0   = blockIdx.x * 128;
    const int mbase = (wid & 3) * 32;
    const int nbase = (wid >> 2) * 64;
    const int lt = lane >> 3;
    const int lr = lane & 7;

    const uint4* srcs[4] = { A0, A1, A2, A3 };

    float acc[2][8][4];
#pragma unroll
    for (int mt = 0; mt < 2; mt++)
#pragma unroll
        for (int nt = 0; nt < 8; nt++)
#pragma unroll
            for (int i = 0; i < 4; i++) acc[mt][nt][i] = 0.f;

    uint32_t as_base = (uint32_t)__cvta_generic_to_shared(&As[0][0]);
    uint32_t bs_base = (uint32_t)__cvta_generic_to_shared(&Bs[0][0]);

    // per-thread load coordinates (fixed across iterations)
    const int ar  = tid >> 1;                 // A row 0..127  (2 slots/thread: c4 in {2s})
    const int ac0 = (tid & 1) * 2;            // A col-uint4 base: {0,2}
    const int br  = tid >> 3;                 // B row 0..31... (512 slots: r=slot>>4)
    // recompute per-slot inside loader instead (keeps R5 mapping)

    auto load_tile = [&](int kc, int buf) {
        const uint4* Asrc = srcs[kc >> 2];
        int f4 = (kc & 3) * 4;
        uint32_t abuf = as_base + buf * AS_BYTES;
        uint32_t bbuf = bs_base + buf * BS_BYTES;
#pragma unroll
        for (int s = 0; s < 2; s++) {
            int slot = tid * 2 + s;
            int r = slot >> 2, c4 = slot & 3;
            const void* g = (const void*)(Asrc + (size_t)(m0 + r) * 16 + f4 + c4);
            uint32_t d = abuf + 2u * (r * AS_STRIDE + c4 * 8);
            int sz = (m0 + r < N) ? 16 : 0;
            CP_ASYNC16(d, g, sz);
        }
#pragma unroll
        for (int s = 0; s < 2; s++) {
            int slot = tid * 2 + s;
            int r = slot >> 4, c4 = slot & 15;
            const void* g = (const void*)(Wh + (size_t)(kc * 32 + r) * 128 + c4 * 8);
            uint32_t d = bbuf + 2u * (r * BS_STRIDE + c4 * 8);
            CP_ASYNC16(d, g, 16);
        }
        CP_COMMIT();
    };

    load_tile(0, 0);

#pragma unroll 1
    for (int kc = 0; kc < 16; kc++) {
        int buf = kc & 1;
        CP_WAIT0();
        __syncthreads();
        if (kc + 1 < 16) load_tile(kc + 1, buf ^ 1);

        uint32_t a_off = as_base + buf * AS_BYTES;
        uint32_t b_off = bs_base + buf * BS_BYTES;
#pragma unroll
        for (int kk = 0; kk < 32; kk += 16) {
            uint32_t a[2][4];
#pragma unroll
            for (int mt = 0; mt < 2; mt++) {
                int arow = mbase + mt * 16 + (lt & 1) * 8 + lr;
                int acol = kk + (lt >> 1) * 8;
                ldsm_x4(a[mt][0], a[mt][1], a[mt][2], a[mt][3],
                        a_off + 2u * (arow * AS_STRIDE + acol));
            }
            uint32_t bfr[4][4];
#pragma unroll
            for (int n2 = 0; n2 < 4; n2++) {
                int brow = kk + (lt & 1) * 8 + lr;
                int bcol = nbase + n2 * 16 + (lt >> 1) * 8;
                ldsm_x4_t(bfr[n2][0], bfr[n2][1], bfr[n2][2], bfr[n2][3],
                          b_off + 2u * (brow * BS_STRIDE + bcol));
            }
#pragma unroll
            for (int mt = 0; mt < 2; mt++)
#pragma unroll
                for (int nt = 0; nt < 8; nt++) {
                    int n2 = nt >> 1, p = (nt & 1) * 2;
                    mma16816(acc[mt][nt], a[mt], bfr[n2][p], bfr[n2][p + 1]);
                }
        }
        __syncthreads();
    }

    // epilogue
#pragma unroll
    for (int nt = 0; nt < 8; nt++) {
        int col = nbase + nt * 8 + (lane & 3) * 2;
        float2 bv = *(const float2*)(bias + col);
#pragma unroll
        for (int mt = 0; mt < 2; mt++) {
            int r0 = m0 + mbase + mt * 16 + (lane >> 2);
            if (r0 < N) {
                float2 o0 = make_float2(acc[mt][nt][0] + bv.x,
                                        acc[mt][nt][1] + bv.y);
                *(float2*)(out + (size_t)r0 * 128 + col) = o0;
            }
            int r1 = r0 + 8;
            if (r1 < N) {
                float2 o1 = make_float2(acc[mt][nt][2] + bv.x,
                                        acc[mt][nt][3] + bv.y);
                *(float2*)(out + (size_t)r1 * 128 + col) = o1;
            }
        }
    }
}

// ---------------------------------------------------------------------------
extern "C" void kernel_launch(void* const* d_in, const int* in_sizes, int n_in,
                              void* d_out, int out_size)
{
    const float* x    = (const float*)d_in[0];
    const int*   rows = (const int*)  d_in[1];
    const int*   cols = (const int*)  d_in[2];
    const float* vals = (const float*)d_in[3];
    const float* W    = (const float*)d_in[4];
    const float* b    = (const float*)d_in[5];
    float* out = (float*)d_out;

    int N = in_sizes[0] / F;
    int E = in_sizes[1];

    void *pXh, *pT1h, *pT2h, *pT3h, *pWh;
    cudaGetSymbolAddress(&pXh,  g_xh);
    cudaGetSymbolAddress(&pT1h, g_T1h);
    cudaGetSymbolAddress(&pT2h, g_T2h);
    cudaGetSymbolAddress(&pT3h, g_T3h);
    cudaGetSymbolAddress(&pWh,  g_Wh);
    uint4* xh  = (uint4*)pXh;
    uint4* T1h = (uint4*)pT1h;
    uint4* T2h = (uint4*)pT2h;
    uint4* T3h = (uint4*)pT3h;
    __half* Wh = (__half*)pWh;

    int nScanBlocks = (N + 1023) / 1024;
    int eBlocks = (E + 255) / 256;
    int n4 = (N * F) / 4;

    // ---- fused prep (hist zero + x->fp16 + W convert) ----
    prep_kernel<<<(n4 + 255) / 256, 256>>>((const float4*)x, n4, N, W);

    // ---- CSR build ----
    hist_kernel<<<eBlocks, 256>>>(rows, E);
    scan1_kernel<<<nScanBlocks, 1024>>>(N);
    scan_finalize_kernel<<<nScanBlocks, 1024>>>(N, nScanBlocks, E);
    scatter_kernel<<<eBlocks, 256>>>(rows, cols, vals, E);

    // ---- Chebyshev recurrence (fp16 storage, fp32 math) ----
    int spmmBlocks = (N * 32 + 255) / 256;
    spmm_csr_h_kernel<<<spmmBlocks, 256>>>((const uint2*)xh,  nullptr,
                                           (uint2*)T1h, N, 1.0f,  0.0f);
    spmm_csr_h_kernel<<<spmmBlocks, 256>>>((const uint2*)T1h, (const uint2*)xh,
                                           (uint2*)T2h, N, 2.0f, -1.0f);
    spmm_csr_h_kernel<<<spmmBlocks, 256>>>((const uint2*)T2h, (const uint2*)T1h,
                                           (uint2*)T3h, N, 2.0f, -1.0f);

    // ---- out = [x|T1|T2|T3] @ W^T + b  (tensor cores, pipelined) ----
    int gblocks = (N + 127) / 128;
    gemm_h_kernel<<<gblocks, 256>>>(xh, T1h, T2h, T3h, Wh, b, out, N);
}